// round 10
// baseline (speedup 1.0000x reference)
#include <cuda_runtime.h>
#include <cuda_fp16.h>
#include <cstdint>
#include <cstddef>

// Problem shapes (fixed)
#define BB 8
#define SS 8192
#define DD 512
#define HH 512
#define OO 512
#define M_TOT (BB * SS)   // 65536
#define NCHK 64           // scan chunks per sequence
#define CLEN (SS / NCHK)  // 128
#define NCHAN (BB * HH)   // 4096
#define NCC  (NCHAN * NCHK)  // 262144

// ---------------------------------------------------------------------------
// Scratch (__device__ globals — allocation-free)
// g_cv layout: [m, 1024] fp16, channel j at columns (2j, 2j+1) = (c_j, v_j)
// ---------------------------------------------------------------------------
__device__ __half g_cv[(size_t)M_TOT * 1024];   // 134 MB
__device__ __half g_xh[(size_t)M_TOT * DD];     // 67 MB
__device__ __half g_hh[(size_t)M_TOT * HH];     // 67 MB
__device__ __half g_w1h[(size_t)1024 * DD];     // interleaved rows
__device__ __half g_w2h[(size_t)512  * HH];
__device__ float g_chA[NCC];
__device__ float g_chB[NCC];
__device__ float g_hstart[NCC];

// ---------------------------------------------------------------------------
// Helpers
// ---------------------------------------------------------------------------
__device__ __forceinline__ uint32_t smem_u32(const void* p) {
    uint32_t a;
    asm("{ .reg .u64 t; cvta.to.shared.u64 t, %1; cvt.u32.u64 %0, t; }" : "=r"(a) : "l"(p));
    return a;
}
__device__ __forceinline__ void cp_async16(uint32_t sdst, const void* gsrc) {
    asm volatile("cp.async.cg.shared.global [%0], [%1], 16;" :: "r"(sdst), "l"(gsrc) : "memory");
}
__device__ __forceinline__ void ldsm4(uint32_t* r, uint32_t addr) {
    asm volatile("ldmatrix.sync.aligned.m8n8.x4.shared.b16 {%0,%1,%2,%3}, [%4];"
                 : "=r"(r[0]), "=r"(r[1]), "=r"(r[2]), "=r"(r[3]) : "r"(addr));
}
__device__ __forceinline__ void mma16816(float* c, const uint32_t* a, const uint32_t* b) {
    asm volatile("mma.sync.aligned.m16n8k16.row.col.f32.f16.f16.f32 "
                 "{%0,%1,%2,%3}, {%4,%5,%6,%7}, {%8,%9}, {%0,%1,%2,%3};"
                 : "+f"(c[0]), "+f"(c[1]), "+f"(c[2]), "+f"(c[3])
                 : "r"(a[0]), "r"(a[1]), "r"(a[2]), "r"(a[3]), "r"(b[0]), "r"(b[1]));
}
__device__ __forceinline__ uint32_t swz(uint32_t off) {  // SW128
    return off ^ ((off >> 3) & 0x70);
}
__device__ __forceinline__ float frcp(float x) {
    float r;
    asm("rcp.approx.f32 %0, %1;" : "=f"(r) : "f"(x));
    return r;
}

// Gate math: c = sigmoid(-g), v = sigmoid(g) * G(z)
__device__ __forceinline__ void gate_cv(float z, float g, float& c, float& v) {
    const float eg  = __expf(g);
    const float inv = frcp(1.0f + eg);
    c = inv;
    const float smg = eg * inv;
    float G;
    if (z >= 0.0f) G = z + 0.5f;
    else {
        const float ez = __expf(z);
        G = ez * frcp(1.0f + ez);
    }
    v = smg * G;
}

// ---------------------------------------------------------------------------
// fp16 HMMA GEMM (NT): C[M,Ntot] = A[M,512] * B[Ntot,512]^T, fp32 accum
// 128x128x64 tile, 256 threads (2Mx4N warps, 64x32 warp tile), 3-stage cp.async
// FUSE_GATE: epilogue pairs (z,g) -> (c,v), stored as half2 (GEMM1 path)
// ---------------------------------------------------------------------------
#define KK       512
#define NCHG     (KK / 64)          // 8 K-chunks
#define STAGE_B  32768
#define NSTAGE   3
#define SMEM_DYN (NSTAGE * STAGE_B + 1024)

template <typename OutT, bool FUSE_GATE>
__global__ void __launch_bounds__(256)
gemm_f16_mma(const __half* __restrict__ A,
             const __half* __restrict__ Bw,
             OutT* __restrict__ C,
             int Ntot)
{
    extern __shared__ char dyn_smem[];
    const uint32_t smem_al = (smem_u32(dyn_smem) + 1023u) & ~1023u;

    const int tid  = threadIdx.x;
    const int lane = tid & 31;
    const int wid  = tid >> 5;
    const int wm   = wid & 1;
    const int wn   = wid >> 1;

    const int m0 = blockIdx.y * 128;
    const int n0 = blockIdx.x * 128;

    const char* Ab = (const char*)(A  + (size_t)m0 * KK);
    const char* Bb = (const char*)(Bw + (size_t)n0 * KK);

    const uint32_t aBase = (uint32_t)((wm * 64 + ((lane >> 3) & 1) * 8 + (lane & 7)) * 128
                                      + (lane >> 4) * 16);
    const uint32_t bBase = (uint32_t)((wn * 32 + (lane >> 4) * 8 + (lane & 7)) * 128
                                      + ((lane >> 3) & 1) * 16);

    float acc[4][4][4];
#pragma unroll
    for (int i = 0; i < 4; ++i)
#pragma unroll
        for (int j = 0; j < 4; ++j)
#pragma unroll
            for (int k = 0; k < 4; ++k) acc[i][j][k] = 0.0f;

    auto load_stage = [&](int i) {
        const uint32_t base = smem_al + (i % NSTAGE) * STAGE_B;
        const size_t kofs = (size_t)i * 128;
#pragma unroll
        for (int p = 0; p < 8; ++p) {
            const int idx = tid + p * 256;
            const int r = (idx >> 3) & 127;
            const int c = idx & 7;
            const uint32_t so = swz((uint32_t)(r << 7) + (uint32_t)(c << 4));
            if (idx < 1024)
                cp_async16(base + so,         Ab + (size_t)r * (KK * 2) + kofs + c * 16);
            else
                cp_async16(base + 16384 + so, Bb + (size_t)r * (KK * 2) + kofs + c * 16);
        }
        asm volatile("cp.async.commit_group;" ::: "memory");
    };

    load_stage(0);
    load_stage(1);

    for (int i = 0; i < NCHG; ++i) {
        if (i + 1 < NCHG) asm volatile("cp.async.wait_group 1;" ::: "memory");
        else              asm volatile("cp.async.wait_group 0;" ::: "memory");
        __syncthreads();
        if (i + 2 < NCHG) load_stage(i + 2);

        const uint32_t sA = smem_al + (i % NSTAGE) * STAGE_B;
        const uint32_t sB = sA + 16384;

#pragma unroll
        for (int ks = 0; ks < 4; ++ks) {
            uint32_t afr[4][4], bfr[2][4];
#pragma unroll
            for (int mt = 0; mt < 4; ++mt)
                ldsm4(afr[mt], sA + swz(aBase + (uint32_t)(mt * 2048 + ks * 32)));
#pragma unroll
            for (int q = 0; q < 2; ++q)
                ldsm4(bfr[q], sB + swz(bBase + (uint32_t)(q * 2048 + ks * 32)));
#pragma unroll
            for (int mt = 0; mt < 4; ++mt)
#pragma unroll
                for (int nt = 0; nt < 4; ++nt) {
                    uint32_t b2[2] = { bfr[nt >> 1][(nt & 1) * 2 + 0],
                                       bfr[nt >> 1][(nt & 1) * 2 + 1] };
                    mma16816(acc[mt][nt], afr[mt], b2);
                }
        }
        // No bottom sync: next iteration's top sync protects stage reuse.
    }

    const int er = lane >> 2;
    const int ec = (lane & 3) * 2;   // even -> (z,g) channel pairs when FUSE_GATE
#pragma unroll
    for (int mt = 0; mt < 4; ++mt) {
#pragma unroll
        for (int nt = 0; nt < 4; ++nt) {
            const size_t r0 = (size_t)(m0 + wm * 64 + mt * 16 + er) * Ntot
                              + n0 + wn * 32 + nt * 8 + ec;
            const size_t r1 = r0 + (size_t)8 * Ntot;
            if constexpr (FUSE_GATE) {
                float c0, v0, c1, v1;
                gate_cv(acc[mt][nt][0], acc[mt][nt][1], c0, v0);
                gate_cv(acc[mt][nt][2], acc[mt][nt][3], c1, v1);
                *reinterpret_cast<__half2*>((__half*)C + r0) = __floats2half2_rn(c0, v0);
                *reinterpret_cast<__half2*>((__half*)C + r1) = __floats2half2_rn(c1, v1);
            } else if constexpr (sizeof(OutT) == 2) {
                *reinterpret_cast<__half2*>((__half*)C + r0) =
                    __floats2half2_rn(acc[mt][nt][0], acc[mt][nt][1]);
                *reinterpret_cast<__half2*>((__half*)C + r1) =
                    __floats2half2_rn(acc[mt][nt][2], acc[mt][nt][3]);
            } else {
                *reinterpret_cast<float2*>((float*)C + r0) =
                    make_float2(acc[mt][nt][0], acc[mt][nt][1]);
                *reinterpret_cast<float2*>((float*)C + r1) =
                    make_float2(acc[mt][nt][2], acc[mt][nt][3]);
            }
        }
    }
}

// ---------------------------------------------------------------------------
// fp32 -> fp16 cast (vectorized)
// ---------------------------------------------------------------------------
__global__ void __launch_bounds__(256)
f32_to_f16(const float* __restrict__ in, __half* __restrict__ out, size_t n4)
{
    for (size_t i = (size_t)blockIdx.x * blockDim.x + threadIdx.x; i < n4;
         i += (size_t)gridDim.x * blockDim.x) {
        const float4 v = reinterpret_cast<const float4*>(in)[i];
        reinterpret_cast<__half2*>(out)[i * 2 + 0] = __floats2half2_rn(v.x, v.y);
        reinterpret_cast<__half2*>(out)[i * 2 + 1] = __floats2half2_rn(v.z, v.w);
    }
}

// ---------------------------------------------------------------------------
// W_hg cast + row interleave: out row 2j = in row j (hidden),
//                             out row 2j+1 = in row j+512 (gate)
// ---------------------------------------------------------------------------
__global__ void __launch_bounds__(256)
w1_cast_interleave(const float* __restrict__ in, __half* __restrict__ out)
{
    const size_t n4 = (size_t)1024 * DD / 4;
    for (size_t i = (size_t)blockIdx.x * blockDim.x + threadIdx.x; i < n4;
         i += (size_t)gridDim.x * blockDim.x) {
        const int r = (int)(i / (DD / 4));       // out row 0..1023
        const int c4 = (int)(i % (DD / 4));
        const int j = r >> 1;
        const int src = (r & 1) ? (j + 512) : j;
        const float4 v = reinterpret_cast<const float4*>(in)[(size_t)src * (DD / 4) + c4];
        reinterpret_cast<__half2*>(out)[i * 2 + 0] = __floats2half2_rn(v.x, v.y);
        reinterpret_cast<__half2*>(out)[i * 2 + 1] = __floats2half2_rn(v.z, v.w);
    }
}

// ---------------------------------------------------------------------------
// Scan pass 1: 2 channels/thread, pure FMA. cv[m, 4hc..4hc+3] = (c0,v0,c1,v1)
// ---------------------------------------------------------------------------
__global__ void __launch_bounds__(256)
scan_pass1(const __half* __restrict__ cv,
           float* __restrict__ chA, float* __restrict__ chB)
{
    const int idx = blockIdx.x * blockDim.x + threadIdx.x;  // < NCC/2
    const int hc = idx & 255;        // channel pair (2hc, 2hc+1)
    const int bc = idx >> 8;
    const int b  = bc >> 6;
    const int ck = bc & (NCHK - 1);

    const __half* base = cv + ((size_t)b * SS + (size_t)ck * CLEN) * 1024 + 4 * hc;

    float A0 = 1.0f, h0 = 0.0f, A1 = 1.0f, h1 = 0.0f;
    constexpr int U = 8;
#pragma unroll 1
    for (int s = 0; s < CLEN; s += U) {
        uint2 q[U];
#pragma unroll
        for (int u = 0; u < U; ++u)
            q[u] = *reinterpret_cast<const uint2*>(base + (size_t)(s + u) * 1024);
#pragma unroll
        for (int u = 0; u < U; ++u) {
            const float2 p0 = __half22float2(*reinterpret_cast<const __half2*>(&q[u].x));
            const float2 p1 = __half22float2(*reinterpret_cast<const __half2*>(&q[u].y));
            h0 = fmaf(p0.x, h0, p0.y); A0 *= p0.x;
            h1 = fmaf(p1.x, h1, p1.y); A1 *= p1.x;
        }
    }
    const int cidx = (b * NCHK + ck) * 512 + 2 * hc;
    *reinterpret_cast<float2*>(chA + cidx) = make_float2(A0, A1);
    *reinterpret_cast<float2*>(chB + cidx) = make_float2(h0, h1);
}

// ---------------------------------------------------------------------------
// Scan pass 2: per (b, h) combine chunk summaries -> h_start + h_n
// ---------------------------------------------------------------------------
__global__ void __launch_bounds__(256)
scan_pass2(const float* __restrict__ chA, const float* __restrict__ chB,
           float* __restrict__ hstart, float* __restrict__ hn_out)
{
    const int idx = blockIdx.x * blockDim.x + threadIdx.x;  // < NCHAN
    const int hh = idx & 511;
    const int b  = idx >> 9;

    float h = 0.0f;
#pragma unroll
    for (int ck = 0; ck < NCHK; ++ck) {
        const int cidx = (b * NCHK + ck) * 512 + hh;
        hstart[cidx] = h;
        h = fmaf(chA[cidx], h, chB[cidx]);
    }
    hn_out[idx] = h;
}

// ---------------------------------------------------------------------------
// Scan pass 3: 2 channels/thread, pure FMA; writes fp16 h
// ---------------------------------------------------------------------------
__global__ void __launch_bounds__(256)
scan_pass3(const __half* __restrict__ cv, const float* __restrict__ hstart,
           __half* __restrict__ hout)
{
    const int idx = blockIdx.x * blockDim.x + threadIdx.x;  // < NCC/2
    const int hc = idx & 255;
    const int bc = idx >> 8;
    const int b  = bc >> 6;
    const int ck = bc & (NCHK - 1);

    const __half* base = cv + ((size_t)b * SS + (size_t)ck * CLEN) * 1024 + 4 * hc;
    __half* hb = hout + ((size_t)b * SS + (size_t)ck * CLEN) * HH + 2 * hc;

    const int cidx = (b * NCHK + ck) * 512 + 2 * hc;
    const float2 hs = *reinterpret_cast<const float2*>(hstart + cidx);
    float h0 = hs.x, h1 = hs.y;

    constexpr int U = 8;
#pragma unroll 1
    for (int s = 0; s < CLEN; s += U) {
        uint2 q[U];
#pragma unroll
        for (int u = 0; u < U; ++u)
            q[u] = *reinterpret_cast<const uint2*>(base + (size_t)(s + u) * 1024);
#pragma unroll
        for (int u = 0; u < U; ++u) {
            const float2 p0 = __half22float2(*reinterpret_cast<const __half2*>(&q[u].x));
            const float2 p1 = __half22float2(*reinterpret_cast<const __half2*>(&q[u].y));
            h0 = fmaf(p0.x, h0, p0.y);
            h1 = fmaf(p1.x, h1, p1.y);
            *reinterpret_cast<__half2*>(hb + (size_t)(s + u) * HH) =
                __floats2half2_rn(h0, h1);
        }
    }
}

// ---------------------------------------------------------------------------
// Launch
// ---------------------------------------------------------------------------
extern "C" void kernel_launch(void* const* d_in, const int* in_sizes, int n_in,
                              void* d_out, int out_size)
{
    const float* x     = (const float*)d_in[0];
    const float* W_hg  = (const float*)d_in[2];
    const float* W_out = (const float*)d_in[3];
    float* out = (float*)d_out;

    float *chA, *chB, *hstart;
    __half *cv, *xh, *hh_ptr, *w1h, *w2h;
    cudaGetSymbolAddress((void**)&cv, g_cv);
    cudaGetSymbolAddress((void**)&xh, g_xh);
    cudaGetSymbolAddress((void**)&hh_ptr, g_hh);
    cudaGetSymbolAddress((void**)&w1h, g_w1h);
    cudaGetSymbolAddress((void**)&w2h, g_w2h);
    cudaGetSymbolAddress((void**)&chA, g_chA);
    cudaGetSymbolAddress((void**)&chB, g_chB);
    cudaGetSymbolAddress((void**)&hstart, g_hstart);
    float* hn = out + (size_t)M_TOT * OO;

    cudaFuncSetAttribute((const void*)gemm_f16_mma<__half, true>,
                         cudaFuncAttributeMaxDynamicSharedMemorySize, SMEM_DYN);
    cudaFuncSetAttribute((const void*)gemm_f16_mma<float, false>,
                         cudaFuncAttributeMaxDynamicSharedMemorySize, SMEM_DYN);

    // Casts (W_hg interleaved for gate fusion)
    f32_to_f16<<<2048, 256>>>(x, xh, (size_t)M_TOT * DD / 4);
    w1_cast_interleave<<<128, 256>>>(W_hg, w1h);
    f32_to_f16<<<128, 256>>>(W_out, w2h, (size_t)512 * HH / 4);

    // GEMM1 + fused gates: cv = gate(x @ W_hg^T)
    {
        dim3 grid(1024 / 128, M_TOT / 128);
        gemm_f16_mma<__half, true><<<grid, 256, SMEM_DYN>>>(xh, w1h, cv, 1024);
    }

    // Parallel scan (pure FMA passes)
    scan_pass1<<<(NCC / 2) / 256, 256>>>(cv, chA, chB);
    scan_pass2<<<NCHAN / 256, 256>>>(chA, chB, hstart, hn);
    scan_pass3<<<(NCC / 2) / 256, 256>>>(cv, hstart, hh_ptr);

    // GEMM2: out = h @ W_out^T
    {
        dim3 grid(512 / 128, M_TOT / 128);
        gemm_f16_mma<float, false><<<grid, 256, SMEM_DYN>>>(hh_ptr, w2h, out, 512);
    }
}

// round 12
// speedup vs baseline: 1.2944x; 1.2944x over previous
#include <cuda_runtime.h>
#include <cuda_fp16.h>
#include <cstdint>
#include <cstddef>

// Problem shapes (fixed)
#define BB 8
#define SS 8192
#define DD 512
#define HH 512
#define OO 512
#define M_TOT (BB * SS)   // 65536
#define NCHK 32           // scan chunks per sequence
#define CLEN (SS / NCHK)  // 256
#define NCHAN (BB * HH)   // 4096
#define NCC  (NCHAN * NCHK)  // 131072

// ---------------------------------------------------------------------------
// Scratch (__device__ globals — allocation-free)
// g_zg: [m, 1024] fp16, channel j at cols (2j, 2j+1) = (z_j, g_j)  (GEMM1 out)
// g_cv: [m, 1024] fp16, channel j at cols (2j, 2j+1) = (c_j, v_j)  (pass1 out)
// ---------------------------------------------------------------------------
__device__ __half g_zg[(size_t)M_TOT * 1024];   // 134 MB
__device__ __half g_cv[(size_t)M_TOT * 1024];   // 134 MB
__device__ __half g_xh[(size_t)M_TOT * DD];     // 67 MB
__device__ __half g_hh[(size_t)M_TOT * HH];     // 67 MB
__device__ __half g_w1h[(size_t)1024 * DD];     // interleaved rows
__device__ __half g_w2h[(size_t)512  * HH];
__device__ float g_chA[NCC];
__device__ float g_chB[NCC];
__device__ float g_hstart[NCC];

// ---------------------------------------------------------------------------
// Helpers
// ---------------------------------------------------------------------------
__device__ __forceinline__ uint32_t smem_u32(const void* p) {
    uint32_t a;
    asm("{ .reg .u64 t; cvta.to.shared.u64 t, %1; cvt.u32.u64 %0, t; }" : "=r"(a) : "l"(p));
    return a;
}
__device__ __forceinline__ void cp_async16(uint32_t sdst, const void* gsrc) {
    asm volatile("cp.async.cg.shared.global [%0], [%1], 16;" :: "r"(sdst), "l"(gsrc) : "memory");
}
__device__ __forceinline__ void ldsm4(uint32_t* r, uint32_t addr) {
    asm volatile("ldmatrix.sync.aligned.m8n8.x4.shared.b16 {%0,%1,%2,%3}, [%4];"
                 : "=r"(r[0]), "=r"(r[1]), "=r"(r[2]), "=r"(r[3]) : "r"(addr));
}
__device__ __forceinline__ void mma16816(float* c, const uint32_t* a, const uint32_t* b) {
    asm volatile("mma.sync.aligned.m16n8k16.row.col.f32.f16.f16.f32 "
                 "{%0,%1,%2,%3}, {%4,%5,%6,%7}, {%8,%9}, {%0,%1,%2,%3};"
                 : "+f"(c[0]), "+f"(c[1]), "+f"(c[2]), "+f"(c[3])
                 : "r"(a[0]), "r"(a[1]), "r"(a[2]), "r"(a[3]), "r"(b[0]), "r"(b[1]));
}
__device__ __forceinline__ uint32_t swz(uint32_t off) {  // SW128
    return off ^ ((off >> 3) & 0x70);
}
__device__ __forceinline__ float frcp(float x) {
    float r;
    asm("rcp.approx.f32 %0, %1;" : "=f"(r) : "f"(x));
    return r;
}

// Gate math: c = sigmoid(-g), v = sigmoid(g) * G(z)
__device__ __forceinline__ void gate_cv(float z, float g, float& c, float& v) {
    const float eg  = __expf(g);
    const float inv = frcp(1.0f + eg);
    c = inv;
    const float smg = eg * inv;
    float G;
    if (z >= 0.0f) G = z + 0.5f;
    else {
        const float ez = __expf(z);
        G = ez * frcp(1.0f + ez);
    }
    v = smg * G;
}

// ---------------------------------------------------------------------------
// fp16 HMMA GEMM (NT): C[M,Ntot] = A[M,512] * B[Ntot,512]^T, fp32 accum
// 128x128x64 tile, 256 threads (2Mx4N warps, 64x32 warp tile), 3-stage cp.async
// (Round-6 configuration — best measured. Plain epilogue, fp16 or fp32 out.)
// ---------------------------------------------------------------------------
#define KK       512
#define NCHG     (KK / 64)          // 8 K-chunks
#define STAGE_B  32768
#define NSTAGE   3
#define SMEM_DYN (NSTAGE * STAGE_B + 1024)

template <typename OutT>
__global__ void __launch_bounds__(256)
gemm_f16_mma(const __half* __restrict__ A,
             const __half* __restrict__ Bw,
             OutT* __restrict__ C,
             int Ntot)
{
    extern __shared__ char dyn_smem[];
    const uint32_t smem_al = (smem_u32(dyn_smem) + 1023u) & ~1023u;

    const int tid  = threadIdx.x;
    const int lane = tid & 31;
    const int wid  = tid >> 5;
    const int wm   = wid & 1;
    const int wn   = wid >> 1;

    const int m0 = blockIdx.y * 128;
    const int n0 = blockIdx.x * 128;

    const char* Ab = (const char*)(A  + (size_t)m0 * KK);
    const char* Bb = (const char*)(Bw + (size_t)n0 * KK);

    const uint32_t aBase = (uint32_t)((wm * 64 + ((lane >> 3) & 1) * 8 + (lane & 7)) * 128
                                      + (lane >> 4) * 16);
    const uint32_t bBase = (uint32_t)((wn * 32 + (lane >> 4) * 8 + (lane & 7)) * 128
                                      + ((lane >> 3) & 1) * 16);

    float acc[4][4][4];
#pragma unroll
    for (int i = 0; i < 4; ++i)
#pragma unroll
        for (int j = 0; j < 4; ++j)
#pragma unroll
            for (int k = 0; k < 4; ++k) acc[i][j][k] = 0.0f;

    auto load_stage = [&](int i) {
        const uint32_t base = smem_al + (i % NSTAGE) * STAGE_B;
        const size_t kofs = (size_t)i * 128;
#pragma unroll
        for (int p = 0; p < 8; ++p) {
            const int idx = tid + p * 256;
            const int r = (idx >> 3) & 127;
            const int c = idx & 7;
            const uint32_t so = swz((uint32_t)(r << 7) + (uint32_t)(c << 4));
            if (idx < 1024)
                cp_async16(base + so,         Ab + (size_t)r * (KK * 2) + kofs + c * 16);
            else
                cp_async16(base + 16384 + so, Bb + (size_t)r * (KK * 2) + kofs + c * 16);
        }
        asm volatile("cp.async.commit_group;" ::: "memory");
    };

    load_stage(0);
    load_stage(1);

    for (int i = 0; i < NCHG; ++i) {
        if (i + 1 < NCHG) asm volatile("cp.async.wait_group 1;" ::: "memory");
        else              asm volatile("cp.async.wait_group 0;" ::: "memory");
        __syncthreads();
        if (i + 2 < NCHG) load_stage(i + 2);

        const uint32_t sA = smem_al + (i % NSTAGE) * STAGE_B;
        const uint32_t sB = sA + 16384;

#pragma unroll
        for (int ks = 0; ks < 4; ++ks) {
            uint32_t afr[4][4], bfr[2][4];
#pragma unroll
            for (int mt = 0; mt < 4; ++mt)
                ldsm4(afr[mt], sA + swz(aBase + (uint32_t)(mt * 2048 + ks * 32)));
#pragma unroll
            for (int q = 0; q < 2; ++q)
                ldsm4(bfr[q], sB + swz(bBase + (uint32_t)(q * 2048 + ks * 32)));
#pragma unroll
            for (int mt = 0; mt < 4; ++mt)
#pragma unroll
                for (int nt = 0; nt < 4; ++nt) {
                    uint32_t b2[2] = { bfr[nt >> 1][(nt & 1) * 2 + 0],
                                       bfr[nt >> 1][(nt & 1) * 2 + 1] };
                    mma16816(acc[mt][nt], afr[mt], b2);
                }
        }
        // No bottom sync: next iteration's top sync protects stage reuse.
    }

    const int er = lane >> 2;
    const int ec = (lane & 3) * 2;
#pragma unroll
    for (int mt = 0; mt < 4; ++mt) {
#pragma unroll
        for (int nt = 0; nt < 4; ++nt) {
            const size_t r0 = (size_t)(m0 + wm * 64 + mt * 16 + er) * Ntot
                              + n0 + wn * 32 + nt * 8 + ec;
            const size_t r1 = r0 + (size_t)8 * Ntot;
            if constexpr (sizeof(OutT) == 2) {
                *reinterpret_cast<__half2*>((__half*)C + r0) =
                    __floats2half2_rn(acc[mt][nt][0], acc[mt][nt][1]);
                *reinterpret_cast<__half2*>((__half*)C + r1) =
                    __floats2half2_rn(acc[mt][nt][2], acc[mt][nt][3]);
            } else {
                *reinterpret_cast<float2*>((float*)C + r0) =
                    make_float2(acc[mt][nt][0], acc[mt][nt][1]);
                *reinterpret_cast<float2*>((float*)C + r1) =
                    make_float2(acc[mt][nt][2], acc[mt][nt][3]);
            }
        }
    }
}

// ---------------------------------------------------------------------------
// fp32 -> fp16 cast (vectorized)
// ---------------------------------------------------------------------------
__global__ void __launch_bounds__(256)
f32_to_f16(const float* __restrict__ in, __half* __restrict__ out, size_t n4)
{
    for (size_t i = (size_t)blockIdx.x * blockDim.x + threadIdx.x; i < n4;
         i += (size_t)gridDim.x * blockDim.x) {
        const float4 v = reinterpret_cast<const float4*>(in)[i];
        reinterpret_cast<__half2*>(out)[i * 2 + 0] = __floats2half2_rn(v.x, v.y);
        reinterpret_cast<__half2*>(out)[i * 2 + 1] = __floats2half2_rn(v.z, v.w);
    }
}

// ---------------------------------------------------------------------------
// W_hg cast + row interleave: out row 2j = in row j (hidden),
//                             out row 2j+1 = in row j+512 (gate)
// => GEMM1 column pair (2j, 2j+1) = (z_j, g_j)
// ---------------------------------------------------------------------------
__global__ void __launch_bounds__(256)
w1_cast_interleave(const float* __restrict__ in, __half* __restrict__ out)
{
    const size_t n4 = (size_t)1024 * DD / 4;
    for (size_t i = (size_t)blockIdx.x * blockDim.x + threadIdx.x; i < n4;
         i += (size_t)gridDim.x * blockDim.x) {
        const int r = (int)(i / (DD / 4));       // out row 0..1023
        const int c4 = (int)(i % (DD / 4));
        const int j = r >> 1;
        const int src = (r & 1) ? (j + 512) : j;
        const float4 v = reinterpret_cast<const float4*>(in)[(size_t)src * (DD / 4) + c4];
        reinterpret_cast<__half2*>(out)[i * 2 + 0] = __floats2half2_rn(v.x, v.y);
        reinterpret_cast<__half2*>(out)[i * 2 + 1] = __floats2half2_rn(v.z, v.w);
    }
}

// ---------------------------------------------------------------------------
// Scan pass 1: one channel/thread. Reads (z,g) half2, computes (c,v),
// writes cv half2, accumulates A = prod c, B = local scan from 0.
// ---------------------------------------------------------------------------
__global__ void __launch_bounds__(256)
scan_pass1(const __half* __restrict__ zg, __half* __restrict__ cv,
           float* __restrict__ chA, float* __restrict__ chB)
{
    const int idx = blockIdx.x * blockDim.x + threadIdx.x;  // < NCC
    const int hh = idx & 511;
    const int bc = idx >> 9;
    const int b  = bc >> 5;
    const int ck = bc & (NCHK - 1);

    const size_t rowbase = ((size_t)b * SS + (size_t)ck * CLEN) * 1024 + 2 * hh;
    const __half* src = zg + rowbase;
    __half*       dst = cv + rowbase;

    float A = 1.0f, h = 0.0f;
    constexpr int U = 8;
#pragma unroll 1
    for (int s = 0; s < CLEN; s += U) {
        __half2 q[U];
#pragma unroll
        for (int u = 0; u < U; ++u)
            q[u] = *reinterpret_cast<const __half2*>(src + (size_t)(s + u) * 1024);
#pragma unroll
        for (int u = 0; u < U; ++u) {
            const float2 p = __half22float2(q[u]);   // (z, g)
            float c, v;
            gate_cv(p.x, p.y, c, v);
            h = fmaf(c, h, v);
            A *= c;
            *reinterpret_cast<__half2*>(dst + (size_t)(s + u) * 1024) =
                __floats2half2_rn(c, v);
        }
    }
    chA[idx] = A;
    chB[idx] = h;
}

// ---------------------------------------------------------------------------
// Scan pass 2: per (b, h) combine chunk summaries -> h_start + h_n
// ---------------------------------------------------------------------------
__global__ void __launch_bounds__(256)
scan_pass2(const float* __restrict__ chA, const float* __restrict__ chB,
           float* __restrict__ hstart, float* __restrict__ hn_out)
{
    const int idx = blockIdx.x * blockDim.x + threadIdx.x;  // < NCHAN
    const int hh = idx & 511;
    const int b  = idx >> 9;

    float h = 0.0f;
#pragma unroll
    for (int ck = 0; ck < NCHK; ++ck) {
        const int cidx = (b * NCHK + ck) * 512 + hh;
        hstart[cidx] = h;
        h = fmaf(chA[cidx], h, chB[cidx]);
    }
    hn_out[idx] = h;
}

// ---------------------------------------------------------------------------
// Scan pass 3: one channel/thread, pure FMA over cv; writes fp16 h.
// ---------------------------------------------------------------------------
__global__ void __launch_bounds__(256)
scan_pass3(const __half* __restrict__ cv, const float* __restrict__ hstart,
           __half* __restrict__ hout)
{
    const int idx = blockIdx.x * blockDim.x + threadIdx.x;  // < NCC
    const int hh = idx & 511;
    const int bc = idx >> 9;
    const int b  = bc >> 5;
    const int ck = bc & (NCHK - 1);

    const __half* src = cv + ((size_t)b * SS + (size_t)ck * CLEN) * 1024 + 2 * hh;
    __half* hb = hout + ((size_t)b * SS + (size_t)ck * CLEN) * HH + hh;

    float h = hstart[idx];
    constexpr int U = 8;
#pragma unroll 1
    for (int s = 0; s < CLEN; s += U) {
        __half2 q[U];
#pragma unroll
        for (int u = 0; u < U; ++u)
            q[u] = *reinterpret_cast<const __half2*>(src + (size_t)(s + u) * 1024);
#pragma unroll
        for (int u = 0; u < U; ++u) {
            const float2 p = __half22float2(q[u]);   // (c, v)
            h = fmaf(p.x, h, p.y);
            hb[(size_t)(s + u) * HH] = __float2half(h);
        }
    }
}

// ---------------------------------------------------------------------------
// Launch
// ---------------------------------------------------------------------------
extern "C" void kernel_launch(void* const* d_in, const int* in_sizes, int n_in,
                              void* d_out, int out_size)
{
    const float* x     = (const float*)d_in[0];
    const float* W_hg  = (const float*)d_in[2];
    const float* W_out = (const float*)d_in[3];
    float* out = (float*)d_out;

    float *chA, *chB, *hstart;
    __half *zg, *cv, *xh, *hh_ptr, *w1h, *w2h;
    cudaGetSymbolAddress((void**)&zg, g_zg);
    cudaGetSymbolAddress((void**)&cv, g_cv);
    cudaGetSymbolAddress((void**)&xh, g_xh);
    cudaGetSymbolAddress((void**)&hh_ptr, g_hh);
    cudaGetSymbolAddress((void**)&w1h, g_w1h);
    cudaGetSymbolAddress((void**)&w2h, g_w2h);
    cudaGetSymbolAddress((void**)&chA, g_chA);
    cudaGetSymbolAddress((void**)&chB, g_chB);
    cudaGetSymbolAddress((void**)&hstart, g_hstart);
    float* hn = out + (size_t)M_TOT * OO;

    cudaFuncSetAttribute((const void*)gemm_f16_mma<__half>,
                         cudaFuncAttributeMaxDynamicSharedMemorySize, SMEM_DYN);
    cudaFuncSetAttribute((const void*)gemm_f16_mma<float>,
                         cudaFuncAttributeMaxDynamicSharedMemorySize, SMEM_DYN);

    // Casts (W_hg interleaved so GEMM1 emits (z,g) channel pairs)
    f32_to_f16<<<2048, 256>>>(x, xh, (size_t)M_TOT * DD / 4);
    w1_cast_interleave<<<128, 256>>>(W_hg, w1h);
    f32_to_f16<<<128, 256>>>(W_out, w2h, (size_t)512 * HH / 4);

    // GEMM1: zg = x @ W_hg^T (interleaved), fp16 out
    {
        dim3 grid(1024 / 128, M_TOT / 128);
        gemm_f16_mma<__half><<<grid, 256, SMEM_DYN>>>(xh, w1h, zg, 1024);
    }

    // Parallel scan: pass1 computes gates once (writes cv), pass3 pure FMA
    scan_pass1<<<NCC / 256, 256>>>(zg, cv, chA, chB);
    scan_pass2<<<NCHAN / 256, 256>>>(chA, chB, hstart, hn);
    scan_pass3<<<NCC / 256, 256>>>(cv, hstart, hh_ptr);

    // GEMM2: out = h @ W_out^T, fp32 out
    {
        dim3 grid(512 / 128, M_TOT / 128);
        gemm_f16_mma<float><<<grid, 256, SMEM_DYN>>>(hh_ptr, w2h, out, 512);
    }
}

// round 13
// speedup vs baseline: 1.2998x; 1.0042x over previous
#include <cuda_runtime.h>
#include <cuda_fp16.h>
#include <cstdint>
#include <cstddef>

// Problem shapes (fixed)
#define BB 8
#define SS 8192
#define DD 512
#define HH 512
#define OO 512
#define M_TOT (BB * SS)   // 65536
#define NCHK 32           // scan chunks per sequence
#define CLEN (SS / NCHK)  // 256
#define NCHAN (BB * HH)   // 4096
#define NCC  (NCHAN * NCHK)  // 131072

// ---------------------------------------------------------------------------
// Scratch (__device__ globals — allocation-free)
// g_zg: [m, 1024] fp16, channel j at cols (2j, 2j+1) = (z_j, g_j)  (GEMM1 out)
// ---------------------------------------------------------------------------
__device__ __half g_zg[(size_t)M_TOT * 1024];   // 134 MB
__device__ __half g_xh[(size_t)M_TOT * DD];     // 67 MB
__device__ __half g_hh[(size_t)M_TOT * HH];     // 67 MB
__device__ __half g_w1h[(size_t)1024 * DD];     // interleaved rows
__device__ __half g_w2h[(size_t)512  * HH];
__device__ float g_chA[NCC];
__device__ float g_chB[NCC];
__device__ float g_hstart[NCC];

// ---------------------------------------------------------------------------
// Helpers
// ---------------------------------------------------------------------------
__device__ __forceinline__ uint32_t smem_u32(const void* p) {
    uint32_t a;
    asm("{ .reg .u64 t; cvta.to.shared.u64 t, %1; cvt.u32.u64 %0, t; }" : "=r"(a) : "l"(p));
    return a;
}
__device__ __forceinline__ void cp_async16(uint32_t sdst, const void* gsrc) {
    asm volatile("cp.async.cg.shared.global [%0], [%1], 16;" :: "r"(sdst), "l"(gsrc) : "memory");
}
__device__ __forceinline__ void ldsm4(uint32_t* r, uint32_t addr) {
    asm volatile("ldmatrix.sync.aligned.m8n8.x4.shared.b16 {%0,%1,%2,%3}, [%4];"
                 : "=r"(r[0]), "=r"(r[1]), "=r"(r[2]), "=r"(r[3]) : "r"(addr));
}
__device__ __forceinline__ void mma16816(float* c, const uint32_t* a, const uint32_t* b) {
    asm volatile("mma.sync.aligned.m16n8k16.row.col.f32.f16.f16.f32 "
                 "{%0,%1,%2,%3}, {%4,%5,%6,%7}, {%8,%9}, {%0,%1,%2,%3};"
                 : "+f"(c[0]), "+f"(c[1]), "+f"(c[2]), "+f"(c[3])
                 : "r"(a[0]), "r"(a[1]), "r"(a[2]), "r"(a[3]), "r"(b[0]), "r"(b[1]));
}
__device__ __forceinline__ uint32_t swz(uint32_t off) {  // SW128
    return off ^ ((off >> 3) & 0x70);
}
__device__ __forceinline__ float frcp(float x) {
    float r;
    asm("rcp.approx.f32 %0, %1;" : "=f"(r) : "f"(x));
    return r;
}

// Gate math: c = sigmoid(-g), v = sigmoid(g) * G(z)
__device__ __forceinline__ void gate_cv(float z, float g, float& c, float& v) {
    const float eg  = __expf(g);
    const float inv = frcp(1.0f + eg);
    c = inv;
    const float smg = eg * inv;
    float G;
    if (z >= 0.0f) G = z + 0.5f;
    else {
        const float ez = __expf(z);
        G = ez * frcp(1.0f + ez);
    }
    v = smg * G;
}

// ---------------------------------------------------------------------------
// fp16 HMMA GEMM (NT): C[M,Ntot] = A[M,512] * B[Ntot,512]^T, fp32 accum
// 128x128x64 tile, 256 threads (2Mx4N warps, 64x32 warp tile), 3-stage cp.async
// (Known-best configuration — do not perturb.)
// ---------------------------------------------------------------------------
#define KK       512
#define NCHG     (KK / 64)          // 8 K-chunks
#define STAGE_B  32768
#define NSTAGE   3
#define SMEM_DYN (NSTAGE * STAGE_B + 1024)

template <typename OutT>
__global__ void __launch_bounds__(256)
gemm_f16_mma(const __half* __restrict__ A,
             const __half* __restrict__ Bw,
             OutT* __restrict__ C,
             int Ntot)
{
    extern __shared__ char dyn_smem[];
    const uint32_t smem_al = (smem_u32(dyn_smem) + 1023u) & ~1023u;

    const int tid  = threadIdx.x;
    const int lane = tid & 31;
    const int wid  = tid >> 5;
    const int wm   = wid & 1;
    const int wn   = wid >> 1;

    const int m0 = blockIdx.y * 128;
    const int n0 = blockIdx.x * 128;

    const char* Ab = (const char*)(A  + (size_t)m0 * KK);
    const char* Bb = (const char*)(Bw + (size_t)n0 * KK);

    const uint32_t aBase = (uint32_t)((wm * 64 + ((lane >> 3) & 1) * 8 + (lane & 7)) * 128
                                      + (lane >> 4) * 16);
    const uint32_t bBase = (uint32_t)((wn * 32 + (lane >> 4) * 8 + (lane & 7)) * 128
                                      + ((lane >> 3) & 1) * 16);

    float acc[4][4][4];
#pragma unroll
    for (int i = 0; i < 4; ++i)
#pragma unroll
        for (int j = 0; j < 4; ++j)
#pragma unroll
            for (int k = 0; k < 4; ++k) acc[i][j][k] = 0.0f;

    auto load_stage = [&](int i) {
        const uint32_t base = smem_al + (i % NSTAGE) * STAGE_B;
        const size_t kofs = (size_t)i * 128;
#pragma unroll
        for (int p = 0; p < 8; ++p) {
            const int idx = tid + p * 256;
            const int r = (idx >> 3) & 127;
            const int c = idx & 7;
            const uint32_t so = swz((uint32_t)(r << 7) + (uint32_t)(c << 4));
            if (idx < 1024)
                cp_async16(base + so,         Ab + (size_t)r * (KK * 2) + kofs + c * 16);
            else
                cp_async16(base + 16384 + so, Bb + (size_t)r * (KK * 2) + kofs + c * 16);
        }
        asm volatile("cp.async.commit_group;" ::: "memory");
    };

    load_stage(0);
    load_stage(1);

    for (int i = 0; i < NCHG; ++i) {
        if (i + 1 < NCHG) asm volatile("cp.async.wait_group 1;" ::: "memory");
        else              asm volatile("cp.async.wait_group 0;" ::: "memory");
        __syncthreads();
        if (i + 2 < NCHG) load_stage(i + 2);

        const uint32_t sA = smem_al + (i % NSTAGE) * STAGE_B;
        const uint32_t sB = sA + 16384;

#pragma unroll
        for (int ks = 0; ks < 4; ++ks) {
            uint32_t afr[4][4], bfr[2][4];
#pragma unroll
            for (int mt = 0; mt < 4; ++mt)
                ldsm4(afr[mt], sA + swz(aBase + (uint32_t)(mt * 2048 + ks * 32)));
#pragma unroll
            for (int q = 0; q < 2; ++q)
                ldsm4(bfr[q], sB + swz(bBase + (uint32_t)(q * 2048 + ks * 32)));
#pragma unroll
            for (int mt = 0; mt < 4; ++mt)
#pragma unroll
                for (int nt = 0; nt < 4; ++nt) {
                    uint32_t b2[2] = { bfr[nt >> 1][(nt & 1) * 2 + 0],
                                       bfr[nt >> 1][(nt & 1) * 2 + 1] };
                    mma16816(acc[mt][nt], afr[mt], b2);
                }
        }
        // No bottom sync: next iteration's top sync protects stage reuse.
    }

    const int er = lane >> 2;
    const int ec = (lane & 3) * 2;
#pragma unroll
    for (int mt = 0; mt < 4; ++mt) {
#pragma unroll
        for (int nt = 0; nt < 4; ++nt) {
            const size_t r0 = (size_t)(m0 + wm * 64 + mt * 16 + er) * Ntot
                              + n0 + wn * 32 + nt * 8 + ec;
            const size_t r1 = r0 + (size_t)8 * Ntot;
            if constexpr (sizeof(OutT) == 2) {
                *reinterpret_cast<__half2*>((__half*)C + r0) =
                    __floats2half2_rn(acc[mt][nt][0], acc[mt][nt][1]);
                *reinterpret_cast<__half2*>((__half*)C + r1) =
                    __floats2half2_rn(acc[mt][nt][2], acc[mt][nt][3]);
            } else {
                *reinterpret_cast<float2*>((float*)C + r0) =
                    make_float2(acc[mt][nt][0], acc[mt][nt][1]);
                *reinterpret_cast<float2*>((float*)C + r1) =
                    make_float2(acc[mt][nt][2], acc[mt][nt][3]);
            }
        }
    }
}

// ---------------------------------------------------------------------------
// fp32 -> fp16 cast (vectorized)
// ---------------------------------------------------------------------------
__global__ void __launch_bounds__(256)
f32_to_f16(const float* __restrict__ in, __half* __restrict__ out, size_t n4)
{
    for (size_t i = (size_t)blockIdx.x * blockDim.x + threadIdx.x; i < n4;
         i += (size_t)gridDim.x * blockDim.x) {
        const float4 v = reinterpret_cast<const float4*>(in)[i];
        reinterpret_cast<__half2*>(out)[i * 2 + 0] = __floats2half2_rn(v.x, v.y);
        reinterpret_cast<__half2*>(out)[i * 2 + 1] = __floats2half2_rn(v.z, v.w);
    }
}

// ---------------------------------------------------------------------------
// W_hg cast + row interleave: out row 2j = hidden_j, out row 2j+1 = gate_j
// => GEMM1 column pair (2j, 2j+1) = (z_j, g_j)
// ---------------------------------------------------------------------------
__global__ void __launch_bounds__(256)
w1_cast_interleave(const float* __restrict__ in, __half* __restrict__ out)
{
    const size_t n4 = (size_t)1024 * DD / 4;
    for (size_t i = (size_t)blockIdx.x * blockDim.x + threadIdx.x; i < n4;
         i += (size_t)gridDim.x * blockDim.x) {
        const int r = (int)(i / (DD / 4));       // out row 0..1023
        const int c4 = (int)(i % (DD / 4));
        const int j = r >> 1;
        const int src = (r & 1) ? (j + 512) : j;
        const float4 v = reinterpret_cast<const float4*>(in)[(size_t)src * (DD / 4) + c4];
        reinterpret_cast<__half2*>(out)[i * 2 + 0] = __floats2half2_rn(v.x, v.y);
        reinterpret_cast<__half2*>(out)[i * 2 + 1] = __floats2half2_rn(v.z, v.w);
    }
}

// ---------------------------------------------------------------------------
// Scan pass 1: one channel/thread. Reads (z,g) half2, computes gates,
// accumulates A = prod c, B = local scan from 0. NO stores of cv.
// ---------------------------------------------------------------------------
__global__ void __launch_bounds__(256)
scan_pass1(const __half* __restrict__ zg,
           float* __restrict__ chA, float* __restrict__ chB)
{
    const int idx = blockIdx.x * blockDim.x + threadIdx.x;  // < NCC
    const int hh = idx & 511;
    const int bc = idx >> 9;
    const int b  = bc >> 5;
    const int ck = bc & (NCHK - 1);

    const __half* src = zg + ((size_t)b * SS + (size_t)ck * CLEN) * 1024 + 2 * hh;

    float A = 1.0f, h = 0.0f;
    constexpr int U = 16;
#pragma unroll 1
    for (int s = 0; s < CLEN; s += U) {
        __half2 q[U];
#pragma unroll
        for (int u = 0; u < U; ++u)
            q[u] = *reinterpret_cast<const __half2*>(src + (size_t)(s + u) * 1024);
#pragma unroll
        for (int u = 0; u < U; ++u) {
            const float2 p = __half22float2(q[u]);   // (z, g)
            float c, v;
            gate_cv(p.x, p.y, c, v);
            h = fmaf(c, h, v);
            A *= c;
        }
    }
    chA[idx] = A;
    chB[idx] = h;
}

// ---------------------------------------------------------------------------
// Scan pass 2: per (b, h) combine chunk summaries -> h_start + h_n
// ---------------------------------------------------------------------------
__global__ void __launch_bounds__(256)
scan_pass2(const float* __restrict__ chA, const float* __restrict__ chB,
           float* __restrict__ hstart, float* __restrict__ hn_out)
{
    const int idx = blockIdx.x * blockDim.x + threadIdx.x;  // < NCHAN
    const int hh = idx & 511;
    const int b  = idx >> 9;

    float h = 0.0f;
#pragma unroll
    for (int ck = 0; ck < NCHK; ++ck) {
        const int cidx = (b * NCHK + ck) * 512 + hh;
        hstart[cidx] = h;
        h = fmaf(chA[cidx], h, chB[cidx]);
    }
    hn_out[idx] = h;
}

// ---------------------------------------------------------------------------
// Scan pass 3: one channel/thread. Re-reads zg, recomputes gates (MUFU is
// free under DRAM), replays chunk from h_start, writes fp16 h.
// ---------------------------------------------------------------------------
__global__ void __launch_bounds__(256)
scan_pass3(const __half* __restrict__ zg, const float* __restrict__ hstart,
           __half* __restrict__ hout)
{
    const int idx = blockIdx.x * blockDim.x + threadIdx.x;  // < NCC
    const int hh = idx & 511;
    const int bc = idx >> 9;
    const int b  = bc >> 5;
    const int ck = bc & (NCHK - 1);

    const __half* src = zg + ((size_t)b * SS + (size_t)ck * CLEN) * 1024 + 2 * hh;
    __half* hb = hout + ((size_t)b * SS + (size_t)ck * CLEN) * HH + hh;

    float h = hstart[idx];
    constexpr int U = 16;
#pragma unroll 1
    for (int s = 0; s < CLEN; s += U) {
        __half2 q[U];
#pragma unroll
        for (int u = 0; u < U; ++u)
            q[u] = *reinterpret_cast<const __half2*>(src + (size_t)(s + u) * 1024);
#pragma unroll
        for (int u = 0; u < U; ++u) {
            const float2 p = __half22float2(q[u]);   // (z, g)
            float c, v;
            gate_cv(p.x, p.y, c, v);
            h = fmaf(c, h, v);
            hb[(size_t)(s + u) * HH] = __float2half(h);
        }
    }
}

// ---------------------------------------------------------------------------
// Launch
// ---------------------------------------------------------------------------
extern "C" void kernel_launch(void* const* d_in, const int* in_sizes, int n_in,
                              void* d_out, int out_size)
{
    const float* x     = (const float*)d_in[0];
    const float* W_hg  = (const float*)d_in[2];
    const float* W_out = (const float*)d_in[3];
    float* out = (float*)d_out;

    float *chA, *chB, *hstart;
    __half *zg, *xh, *hh_ptr, *w1h, *w2h;
    cudaGetSymbolAddress((void**)&zg, g_zg);
    cudaGetSymbolAddress((void**)&xh, g_xh);
    cudaGetSymbolAddress((void**)&hh_ptr, g_hh);
    cudaGetSymbolAddress((void**)&w1h, g_w1h);
    cudaGetSymbolAddress((void**)&w2h, g_w2h);
    cudaGetSymbolAddress((void**)&chA, g_chA);
    cudaGetSymbolAddress((void**)&chB, g_chB);
    cudaGetSymbolAddress((void**)&hstart, g_hstart);
    float* hn = out + (size_t)M_TOT * OO;

    cudaFuncSetAttribute((const void*)gemm_f16_mma<__half>,
                         cudaFuncAttributeMaxDynamicSharedMemorySize, SMEM_DYN);
    cudaFuncSetAttribute((const void*)gemm_f16_mma<float>,
                         cudaFuncAttributeMaxDynamicSharedMemorySize, SMEM_DYN);

    // Casts (W_hg interleaved so GEMM1 emits (z,g) channel pairs)
    f32_to_f16<<<2048, 256>>>(x, xh, (size_t)M_TOT * DD / 4);
    w1_cast_interleave<<<128, 256>>>(W_hg, w1h);
    f32_to_f16<<<128, 256>>>(W_out, w2h, (size_t)512 * HH / 4);

    // GEMM1: zg = x @ W_hg^T (interleaved), fp16 out
    {
        dim3 grid(1024 / 128, M_TOT / 128);
        gemm_f16_mma<__half><<<grid, 256, SMEM_DYN>>>(xh, w1h, zg, 1024);
    }

    // Parallel scan: gates recomputed in pass3 (no cv buffer)
    scan_pass1<<<NCC / 256, 256>>>(zg, chA, chB);
    scan_pass2<<<NCHAN / 256, 256>>>(chA, chB, hstart, hn);
    scan_pass3<<<NCC / 256, 256>>>(zg, hstart, hh_ptr);

    // GEMM2: out = h @ W_out^T, fp32 out
    {
        dim3 grid(512 / 128, M_TOT / 128);
        gemm_f16_mma<float><<<grid, 256, SMEM_DYN>>>(hh_ptr, w2h, out, 512);
    }
}